// round 3
// baseline (speedup 1.0000x reference)
#include <cuda_runtime.h>
#include <math.h>

#define BATCH    65536
#define D1       196
#define D2       206
#define NP       208        // padded dim (multiple of 16)
#define NSTR     212        // smem row stride for q/p/sq
#define KC       16         // K-chunk (13 chunks * 16 = 208)
#define KSTR     20         // padded column stride inside Mb (80B: conflict-free LDS.128)
#define NCH      13
#define TM       64         // batch rows per CTA
#define NTHREADS 256
#define DT       0.1f       // 0.5 / 5

__device__ float g_M1[NP * NP];
__device__ float g_M2[NP * NP];

typedef unsigned long long u64;

// pack two floats into a 64-bit f32x2 carrier
__device__ __forceinline__ u64 pk2(float lo, float hi) {
    u64 r;
    asm("mov.b64 %0, {%1,%2};" : "=l"(r) : "f"(lo), "f"(hi));
    return r;
}
// packed fma: d = a*b + d (elementwise f32x2)  [sm_10x FFMA2]
__device__ __forceinline__ void ffma2(u64& d, u64 a, u64 b) {
    asm("fma.rn.f32x2 %0, %1, %2, %0;" : "+l"(d) : "l"(a), "l"(b));
}
// horizontal fold of a packed pair
__device__ __forceinline__ float unpk_sum(u64 v) {
    float lo, hi;
    asm("mov.b64 {%0,%1}, %2;" : "=f"(lo), "=f"(hi) : "l"(v));
    return lo + hi;
}

// Build M = c2q(C) + Qn - I, zero-padded to NP x NP (row-major; M is symmetric).
__global__ void prep_kernel(const float* __restrict__ C,
                            const float* __restrict__ Qn,
                            int n, int which)
{
    float* M = which ? g_M2 : g_M1;
    const int j = blockIdx.x;
    __shared__ float red[NTHREADS];
    float s = 0.f;
    if (j < n) {
        for (int i = threadIdx.x; i < n; i += NTHREADS)
            s += 0.5f * (C[i * n + j] + C[j * n + i]);
    }
    red[threadIdx.x] = s;
    __syncthreads();
    for (int off = NTHREADS / 2; off > 0; off >>= 1) {
        if (threadIdx.x < off) red[threadIdx.x] += red[threadIdx.x + off];
        __syncthreads();
    }
    const float colsum = red[0];
    for (int i = threadIdx.x; i < NP; i += NTHREADS) {
        float v = 0.f;
        if (j < n && i < n) {
            if (i == j) v = -colsum + Qn[j * n + j] - 1.0f;
            else        v = 0.5f * (C[i * n + j] + C[j * n + i]) + Qn[i * n + j];
        }
        M[i * NP + j] = v;
    }
}

__global__ void __launch_bounds__(NTHREADS, 1)
net_kernel(const float* __restrict__ x,
           const float* __restrict__ b1,
           const float* __restrict__ b2,
           const float* __restrict__ facp,
           float* __restrict__ out)
{
    extern __shared__ float sm[];
    float* sqs = sm;                       // TM * NSTR
    float* qs  = sqs + TM * NSTR;          // TM * NSTR
    float* ps  = qs  + TM * NSTR;          // TM * NSTR
    float* Mb  = ps  + TM * NSTR;          // 2 * NP * KSTR (double-buffered M chunks)
    float* es  = Mb  + 2 * NP * KSTR;      // NP (bias, padded 0)

    const int tid  = threadIdx.x;
    const int tx   = tid & 15;             // column group (16)
    const int ty   = tid >> 4;             // row group (16)
    const int row0 = ty * 4;
    const int rowg = blockIdx.x * TM;

    // ---- init stage-1 state: q = x (zero-padded), bias e1 ----
    #pragma unroll
    for (int c = 0; c < 13; c++) {
        const int col = tx + 16 * c;
        #pragma unroll
        for (int r = 0; r < 4; r++) {
            float v = 0.f;
            if (col < D1) v = x[(rowg + row0 + r) * D1 + col];
            qs[(row0 + r) * NSTR + col] = v;
        }
    }
    for (int i = tid; i < NP; i += NTHREADS) es[i] = (i < D1) ? b1[i] : 0.f;
    __syncthreads();

    // sq = sin(1.1 * q) for this thread's own cells (pads stay exactly 0)
    auto calc_sq = [&] {
        #pragma unroll
        for (int c = 0; c < 13; c++) {
            const int col = tx + 16 * c;
            #pragma unroll
            for (int r = 0; r < 4; r++) {
                const int i = (row0 + r) * NSTR + col;
                sqs[i] = __sinf(1.1f * qs[i]);
            }
        }
    };

    u64 acc2[4][13];   // packed even/odd-k partial sums

    // acc[r][c] = sum_k sq[row][k] * M[k][col]   (M symmetric -> read rows)
    auto gemm = [&](const float* __restrict__ Mg) {
        #pragma unroll
        for (int c = 0; c < 13; c++)
            #pragma unroll
            for (int r = 0; r < 4; r++) acc2[r][c] = 0ull;
        // preload chunk 0 into buffer 0 (padded column stride KSTR)
        {
            float4* dst = (float4*)Mb;
            const float4* src = (const float4*)Mg;
            for (int idx = tid; idx < NP * 4; idx += NTHREADS) {
                const int j = idx >> 2, v = idx & 3;
                dst[j * (KSTR / 4) + v] = src[j * (NP / 4) + v];
            }
        }
        __syncthreads();
        for (int ch = 0; ch < NCH; ch++) {
            const float* cur = Mb + (ch & 1) * NP * KSTR;
            if (ch + 1 < NCH) {
                float4* dst = (float4*)(Mb + ((ch + 1) & 1) * NP * KSTR);
                const float4* src = (const float4*)Mg;
                const int co = (ch + 1) * (KC / 4);
                for (int idx = tid; idx < NP * 4; idx += NTHREADS) {
                    const int j = idx >> 2, v = idx & 3;
                    dst[j * (KSTR / 4) + v] = src[j * (NP / 4) + co + v];
                }
            }
            const int k0 = ch * KC;
            #pragma unroll
            for (int k4 = 0; k4 < KC / 4; k4++) {
                u64 sp[4][2];
                #pragma unroll
                for (int r = 0; r < 4; r++) {
                    const float4 sv =
                        *(const float4*)&sqs[(row0 + r) * NSTR + k0 + 4 * k4];
                    sp[r][0] = pk2(sv.x, sv.y);
                    sp[r][1] = pk2(sv.z, sv.w);
                }
                #pragma unroll
                for (int c = 0; c < 13; c++) {
                    const float4 mv =
                        *(const float4*)&cur[(tx + 16 * c) * KSTR + 4 * k4];
                    const u64 mp0 = pk2(mv.x, mv.y);
                    const u64 mp1 = pk2(mv.z, mv.w);
                    #pragma unroll
                    for (int r = 0; r < 4; r++) {
                        ffma2(acc2[r][c], sp[r][0], mp0);
                        ffma2(acc2[r][c], sp[r][1], mp1);
                    }
                }
            }
            __syncthreads();
        }
    };

    // ================= STAGE 1 (3 full evals) =================
    // E0 = g(q0): q <- q0 + dt^2*E0 (=q2), p <- 2dt*E0 (=p2)
    calc_sq(); __syncthreads();
    gemm(g_M1);
    #pragma unroll
    for (int c = 0; c < 13; c++) {
        const int col = tx + 16 * c;
        const float ec = es[col];
        #pragma unroll
        for (int r = 0; r < 4; r++) {
            const int i = (row0 + r) * NSTR + col;
            const float a = ec + unpk_sum(acc2[r][c]);
            qs[i] += DT * DT * a;
            ps[i]  = 2.f * DT * a;
        }
    }
    __syncthreads();
    // E2 = g(q2): q <- q + dt*p (=q3), p <- p + dt*E2 (=p3)
    calc_sq(); __syncthreads();
    gemm(g_M1);
    #pragma unroll
    for (int c = 0; c < 13; c++) {
        const int col = tx + 16 * c;
        const float ec = es[col];
        #pragma unroll
        for (int r = 0; r < 4; r++) {
            const int i = (row0 + r) * NSTR + col;
            const float po = ps[i];
            qs[i] += DT * po;
            ps[i]  = po + DT * (ec + unpk_sum(acc2[r][c]));
        }
    }
    __syncthreads();
    // E3 = g(q3): q5 = q + 2dt*p + dt^2*E3   (p discarded)
    calc_sq(); __syncthreads();
    gemm(g_M1);
    #pragma unroll
    for (int c = 0; c < 13; c++) {
        const int col = tx + 16 * c;
        const float ec = es[col];
        #pragma unroll
        for (int r = 0; r < 4; r++) {
            const int i = (row0 + r) * NSTR + col;
            qs[i] += 2.f * DT * ps[i] + DT * DT * (ec + unpk_sum(acc2[r][c]));
        }
    }
    __syncthreads();

    // ================= STAGE 2 (1 full + 2 skinny evals) =================
    // q cols [196,208) are already exactly 0; p fully overwritten below.
    for (int i = tid; i < NP; i += NTHREADS) es[i] = (i < D2) ? b2[i] : 0.f;
    __syncthreads();
    // E0 full
    calc_sq(); __syncthreads();
    gemm(g_M2);
    #pragma unroll
    for (int c = 0; c < 13; c++) {
        const int col = tx + 16 * c;
        const float ec = es[col];
        #pragma unroll
        for (int r = 0; r < 4; r++) {
            const int i = (row0 + r) * NSTR + col;
            const float a = ec + unpk_sum(acc2[r][c]);
            qs[i] += DT * DT * a;
            ps[i]  = 2.f * DT * a;
        }
    }
    // tail of M2 (columns 196..205) into Mb for the skinny matmuls
    for (int idx = tid; idx < D2 * 10; idx += NTHREADS) {
        const int k = idx / 10, jj = idx - k * 10;
        Mb[k * 12 + jj] = g_M2[k * NP + 196 + jj];
    }
    __syncthreads();

    const int srow = tid >> 2;            // skinny mapping: 64 rows x 4 groups
    const int g    = tid & 3;

    // E2 skinny (last-10 cols only)
    calc_sq(); __syncthreads();
    float a2[3];
    {
        #pragma unroll
        for (int m = 0; m < 3; m++) a2[m] = es[196 + g + 4 * m];
        const float* sr = &sqs[srow * NSTR];
        #pragma unroll 2
        for (int k = 0; k < D2; k++) {
            const float s = sr[k];
            #pragma unroll
            for (int m = 0; m < 3; m++) a2[m] += s * Mb[k * 12 + g + 4 * m];
        }
    }
    // q <- q + dt*p (full, uses old p)
    #pragma unroll
    for (int c = 0; c < 13; c++) {
        const int col = tx + 16 * c;
        #pragma unroll
        for (int r = 0; r < 4; r++) {
            const int i = (row0 + r) * NSTR + col;
            qs[i] += DT * ps[i];
        }
    }
    __syncthreads();
    // p[last10] <- p + dt*E2
    #pragma unroll
    for (int m = 0; m < 3; m++) {
        const int j = 196 + g + 4 * m;
        if (j < D2) ps[srow * NSTR + j] += DT * a2[m];
    }
    __syncthreads();

    // E3 skinny at q3, then output q5 = q3 + 2dt*p3 + dt^2*E3
    calc_sq(); __syncthreads();
    float a3[3];
    {
        #pragma unroll
        for (int m = 0; m < 3; m++) a3[m] = es[196 + g + 4 * m];
        const float* sr = &sqs[srow * NSTR];
        #pragma unroll 2
        for (int k = 0; k < D2; k++) {
            const float s = sr[k];
            #pragma unroll
            for (int m = 0; m < 3; m++) a3[m] += s * Mb[k * 12 + g + 4 * m];
        }
    }
    const float fac = *facp;
    #pragma unroll
    for (int m = 0; m < 3; m++) {
        const int j = 196 + g + 4 * m;
        if (j < D2) {
            const float q5 = qs[srow * NSTR + j]
                           + 2.f * DT * ps[srow * NSTR + j]
                           + DT * DT * a3[m];
            out[(rowg + srow) * 10 + (j - 196)] = fac * q5;
        }
    }
}

extern "C" void kernel_launch(void* const* d_in, const int* in_sizes, int n_in,
                              void* d_out, int out_size)
{
    const float* x    = (const float*)d_in[0];
    const float* fc1w = (const float*)d_in[1];
    const float* fc1b = (const float*)d_in[2];
    const float* fc2w = (const float*)d_in[3];
    const float* fc2b = (const float*)d_in[4];
    const float* fac  = (const float*)d_in[5];
    const float* qn1  = (const float*)d_in[6];
    const float* qn2  = (const float*)d_in[7];
    float* out = (float*)d_out;

    prep_kernel<<<NP, NTHREADS>>>(fc1w, qn1, D1, 0);
    prep_kernel<<<NP, NTHREADS>>>(fc2w, qn2, D2, 1);

    const int smem = (3 * TM * NSTR + 2 * NP * KSTR + NP) * (int)sizeof(float);
    cudaFuncSetAttribute(net_kernel,
                         cudaFuncAttributeMaxDynamicSharedMemorySize, smem);
    net_kernel<<<BATCH / TM, NTHREADS, smem>>>(x, fc1b, fc2b, fac, out);
}

// round 4
// speedup vs baseline: 1.3218x; 1.3218x over previous
#include <cuda_runtime.h>
#include <cuda_bf16.h>
#include <math.h>

#define BATCH    65536
#define D1       196
#define D2       206
#define NP       208        // padded dim
#define TM       64         // batch rows per CTA
#define NTHREADS 256
#define DT       0.1f
#define DT2      0.01f
#define NKT      13         // k16 tiles (208/16)
#define NNT      26         // n8 octets (208/8)
#define CHUNK_U4 (NNT * 32) // uint4 per k16 B-chunk = 832

__device__ float g_M1[NP * NP];
__device__ float g_M2[NP * NP];
__device__ uint4 g_B1[NKT * NNT * 32];   // pre-fragmented bf16x3 B (stage 1)
__device__ uint4 g_B2[NKT * NNT * 32];   // stage 2

// ---------- helpers ----------
__device__ __forceinline__ unsigned pack_bf2(float lo, float hi) {
    __nv_bfloat162 v = __floats2bfloat162_rn(lo, hi);  // .x = lo (even k)
    return *reinterpret_cast<unsigned*>(&v);
}
// split (s0,s1) into bf16 hi pair + bf16 residual pair
__device__ __forceinline__ void split2(float s0, float s1,
                                       unsigned& hi, unsigned& lo) {
    float h0 = __bfloat162float(__float2bfloat16_rn(s0));
    float h1 = __bfloat162float(__float2bfloat16_rn(s1));
    hi = pack_bf2(h0, h1);
    lo = pack_bf2(s0 - h0, s1 - h1);
}
__device__ __forceinline__ void mma16816(float (&d)[4],
                                         unsigned a0, unsigned a1,
                                         unsigned a2, unsigned a3,
                                         unsigned b0, unsigned b1) {
    asm volatile(
        "mma.sync.aligned.m16n8k16.row.col.f32.bf16.bf16.f32 "
        "{%0,%1,%2,%3}, {%4,%5,%6,%7}, {%8,%9}, {%0,%1,%2,%3};"
        : "+f"(d[0]), "+f"(d[1]), "+f"(d[2]), "+f"(d[3])
        : "r"(a0), "r"(a1), "r"(a2), "r"(a3), "r"(b0), "r"(b1));
}

// ---------- prep 1: M = c2q(C) + Qn - I, zero-padded to NP x NP ----------
__global__ void prep_kernel(const float* __restrict__ C,
                            const float* __restrict__ Qn,
                            int n, int which)
{
    float* M = which ? g_M2 : g_M1;
    const int j = blockIdx.x;
    __shared__ float red[NTHREADS];
    float s = 0.f;
    if (j < n) {
        for (int i = threadIdx.x; i < n; i += NTHREADS)
            s += 0.5f * (C[i * n + j] + C[j * n + i]);
    }
    red[threadIdx.x] = s;
    __syncthreads();
    for (int off = NTHREADS / 2; off > 0; off >>= 1) {
        if (threadIdx.x < off) red[threadIdx.x] += red[threadIdx.x + off];
        __syncthreads();
    }
    const float colsum = red[0];
    for (int i = threadIdx.x; i < NP; i += NTHREADS) {
        float v = 0.f;
        if (j < n && i < n) {
            if (i == j) v = -colsum + Qn[j * n + j] - 1.0f;
            else        v = 0.5f * (C[i * n + j] + C[j * n + i]) + Qn[i * n + j];
        }
        M[i * NP + j] = v;
    }
}

// ---------- prep 2: pack M into mma b-fragment layout (hi/lo splits) ----------
// b0 of tile (kt,nt): B[k=16kt+2t+{0,1}][n=8nt+g]; b1: k offset +8. (g=lane>>2,t=lane&3)
__global__ void prep_frag(int which)
{
    const float* M = which ? g_M2 : g_M1;
    uint4* outB    = which ? g_B2 : g_B1;
    const int idx = blockIdx.x * blockDim.x + threadIdx.x;
    if (idx >= NKT * NNT * 32) return;
    const int lane = idx & 31;
    const int nt   = (idx >> 5) % NNT;
    const int kt   = (idx >> 5) / NNT;
    const int n  = nt * 8 + (lane >> 2);
    const int k0 = kt * 16 + (lane & 3) * 2;
    unsigned bh0, bl0, bh1, bl1;
    split2(M[k0 * NP + n],       M[(k0 + 1) * NP + n], bh0, bl0);
    split2(M[(k0 + 8) * NP + n], M[(k0 + 9) * NP + n], bh1, bl1);
    outB[(kt * NNT + nt) * 32 + lane] = make_uint4(bh0, bh1, bl0, bl1);
}

// ---------- main fused kernel ----------
__global__ void __launch_bounds__(NTHREADS, 1)
net_kernel(const float* __restrict__ x,
           const float* __restrict__ b1,
           const float* __restrict__ b2,
           const float* __restrict__ facp,
           float* __restrict__ out)
{
    extern __shared__ char smraw[];
    unsigned* Afrag = (unsigned*)smraw;                 // 4 rt * 13 kt * 8 slots * 32
    uint4*    Bs    = (uint4*)(Afrag + 4 * NKT * 8 * 32);
    float*    p_s   = (float*)(Bs + 2 * CHUNK_U4);      // 52 slots * 256 threads
    float*    es    = p_s + 52 * NTHREADS;              // NP bias

    const int tid  = threadIdx.x;
    const int lane = tid & 31, warp = tid >> 5;
    const int rt = warp & 3;        // row-tile (16 rows)
    const int h  = warp >> 2;       // col half (104 cols)
    const int g  = lane >> 2, t = lane & 3;
    const int rowg = blockIdx.x * TM;
    const int r0 = rt * 16 + g;     // owned local rows r0, r0+8

    float q[13][4];
    float acc[13][4];

    // init q = x (zero-padded); col pairs never straddle 196 (even boundary)
    #pragma unroll
    for (int nt = 0; nt < 13; nt++) {
        const int col = (h * 13 + nt) * 8 + 2 * t;
        if (col < D1) {
            const float2 v0 = *(const float2*)&x[(rowg + r0) * D1 + col];
            const float2 v1 = *(const float2*)&x[(rowg + r0 + 8) * D1 + col];
            q[nt][0] = v0.x; q[nt][1] = v0.y; q[nt][2] = v1.x; q[nt][3] = v1.y;
        } else {
            q[nt][0] = q[nt][1] = q[nt][2] = q[nt][3] = 0.f;
        }
    }
    for (int i = tid; i < NP; i += NTHREADS) es[i] = (i < D1) ? b1[i] : 0.f;
    __syncthreads();

    // sq = sin(1.1*q) -> bf16 hi/lo A-fragments in smem
    auto write_A = [&] {
        #pragma unroll
        for (int nt = 0; nt < 13; nt++) {
            const int NT = h * 13 + nt;
            const int kt = NT >> 1;
            const int rb = (NT & 1) ? 2 : 0;
            unsigned* base = &Afrag[((rt * 13 + kt) * 8) * 32 + lane];
            unsigned hi, lo;
            split2(__sinf(1.1f * q[nt][0]), __sinf(1.1f * q[nt][1]), hi, lo);
            base[rb * 32]       = hi;
            base[(rb + 4) * 32] = lo;
            split2(__sinf(1.1f * q[nt][2]), __sinf(1.1f * q[nt][3]), hi, lo);
            base[(rb + 1) * 32] = hi;
            base[(rb + 5) * 32] = lo;
        }
    };

    // acc = e + sq @ M  (bf16x3: ah*bh + ah*bl + al*bh), B streamed per k16 chunk
    auto gemm = [&](const uint4* __restrict__ Bg) {
        #pragma unroll
        for (int nt = 0; nt < 13; nt++) {
            const float2 e = *(const float2*)&es[(h * 13 + nt) * 8 + 2 * t];
            acc[nt][0] = e.x; acc[nt][1] = e.y; acc[nt][2] = e.x; acc[nt][3] = e.y;
        }
        for (int i = tid; i < CHUNK_U4; i += NTHREADS) Bs[i] = Bg[i];
        __syncthreads();                       // also orders write_A -> reads
        for (int kt = 0; kt < NKT; kt++) {
            if (kt + 1 < NKT) {
                const uint4* src = Bg + (kt + 1) * CHUNK_U4;
                uint4* dst = Bs + ((kt + 1) & 1) * CHUNK_U4;
                for (int i = tid; i < CHUNK_U4; i += NTHREADS) dst[i] = src[i];
            }
            const unsigned* Ab = &Afrag[((rt * 13 + kt) * 8) * 32 + lane];
            const unsigned ah0 = Ab[0],   ah1 = Ab[32],  ah2 = Ab[64],  ah3 = Ab[96];
            const unsigned al0 = Ab[128], al1 = Ab[160], al2 = Ab[192], al3 = Ab[224];
            const uint4* Bw = Bs + (kt & 1) * CHUNK_U4 + (h * 13) * 32 + lane;
            #pragma unroll
            for (int nt = 0; nt < 13; nt++) {
                const uint4 b = Bw[nt * 32];
                mma16816(acc[nt], ah0, ah1, ah2, ah3, b.x, b.y);  // ah*bh
                mma16816(acc[nt], ah0, ah1, ah2, ah3, b.z, b.w);  // ah*bl
                mma16816(acc[nt], al0, al1, al2, al3, b.x, b.y);  // al*bh
            }
            __syncthreads();
        }
    };

    #define PIDX(nt, j) ((nt) * 4 + (j)) * NTHREADS + tid

    // one PAT stage: evals at q0, q2, q3 (p0 = 0 algebra)
    auto stage = [&](const uint4* Bg) {
        // E0: q += dt^2*a ; p = 2dt*a
        write_A(); gemm(Bg);
        #pragma unroll
        for (int nt = 0; nt < 13; nt++)
            #pragma unroll
            for (int j = 0; j < 4; j++) {
                const float a = acc[nt][j];
                q[nt][j] += DT2 * a;
                p_s[PIDX(nt, j)] = 2.f * DT * a;
            }
        // E2: q += dt*p ; p += dt*a
        write_A(); gemm(Bg);
        #pragma unroll
        for (int nt = 0; nt < 13; nt++)
            #pragma unroll
            for (int j = 0; j < 4; j++) {
                const float po = p_s[PIDX(nt, j)];
                q[nt][j] += DT * po;
                p_s[PIDX(nt, j)] = po + DT * acc[nt][j];
            }
        // E3: q += 2dt*p + dt^2*a
        write_A(); gemm(Bg);
        #pragma unroll
        for (int nt = 0; nt < 13; nt++)
            #pragma unroll
            for (int j = 0; j < 4; j++)
                q[nt][j] += 2.f * DT * p_s[PIDX(nt, j)] + DT2 * acc[nt][j];
    };

    // ---- stage 1 ----
    stage(g_B1);

    // ---- stage 2: new bias; q pads (>=196) are still exactly 0; p overwritten at E0 ----
    __syncthreads();
    for (int i = tid; i < NP; i += NTHREADS) es[i] = (i < D2) ? b2[i] : 0.f;
    __syncthreads();
    stage(g_B2);

    // ---- output: cols 196..205 ----
    const float fac = *facp;
    if (h == 1) {
        #pragma unroll
        for (int nt = 11; nt < 13; nt++) {
            const int col0 = (13 + nt) * 8 + 2 * t;
            #pragma unroll
            for (int jj = 0; jj < 2; jj++) {
                const int col = col0 + jj;
                if (col >= 196 && col < D2) {
                    out[(rowg + r0) * 10 + (col - 196)]     = fac * q[nt][jj];
                    out[(rowg + r0 + 8) * 10 + (col - 196)] = fac * q[nt][2 + jj];
                }
            }
        }
    }
}

extern "C" void kernel_launch(void* const* d_in, const int* in_sizes, int n_in,
                              void* d_out, int out_size)
{
    const float* x    = (const float*)d_in[0];
    const float* fc1w = (const float*)d_in[1];
    const float* fc1b = (const float*)d_in[2];
    const float* fc2w = (const float*)d_in[3];
    const float* fc2b = (const float*)d_in[4];
    const float* fac  = (const float*)d_in[5];
    const float* qn1  = (const float*)d_in[6];
    const float* qn2  = (const float*)d_in[7];
    float* out = (float*)d_out;

    prep_kernel<<<NP, NTHREADS>>>(fc1w, qn1, D1, 0);
    prep_kernel<<<NP, NTHREADS>>>(fc2w, qn2, D2, 1);
    const int nfrag = NKT * NNT * 32;
    prep_frag<<<(nfrag + NTHREADS - 1) / NTHREADS, NTHREADS>>>(0);
    prep_frag<<<(nfrag + NTHREADS - 1) / NTHREADS, NTHREADS>>>(1);

    const int smem = (4 * NKT * 8 * 32) * 4      // A frags
                   + 2 * CHUNK_U4 * 16           // B double buffer
                   + 52 * NTHREADS * 4           // p
                   + NP * 4;                     // bias
    cudaFuncSetAttribute(net_kernel,
                         cudaFuncAttributeMaxDynamicSharedMemorySize, smem);
    net_kernel<<<BATCH / TM, NTHREADS, smem>>>(x, fc1b, fc2b, fac, out);
}

// round 5
// speedup vs baseline: 1.3232x; 1.0011x over previous
#include <cuda_runtime.h>
#include <cuda_bf16.h>
#include <math.h>

#define BATCH    65536
#define D1       196
#define D2       206
#define NP       208        // padded dim
#define TM       64         // batch rows per CTA
#define NTHREADS 256
#define DT       0.1f
#define DT2      0.01f
#define NKT      13         // k16 tiles (208/16)
#define NNT      26         // n8 octets (208/8)
#define CHUNK_U4 (NNT * 32) // uint4 per k16 B-chunk = 832

__device__ float g_M1[NP * NP];
__device__ float g_M2[NP * NP];
__device__ uint4 g_B1[NKT * NNT * 32];   // pre-fragmented bf16x3 B (stage 1)
__device__ uint4 g_B2[NKT * NNT * 32];   // stage 2

// ---------- helpers ----------
__device__ __forceinline__ unsigned pack_bf2(float lo, float hi) {
    __nv_bfloat162 v = __floats2bfloat162_rn(lo, hi);  // .x = lo (even k)
    return *reinterpret_cast<unsigned*>(&v);
}
// split (s0,s1) into bf16 hi pair + bf16 residual pair
__device__ __forceinline__ void split2(float s0, float s1,
                                       unsigned& hi, unsigned& lo) {
    float h0 = __bfloat162float(__float2bfloat16_rn(s0));
    float h1 = __bfloat162float(__float2bfloat16_rn(s1));
    hi = pack_bf2(h0, h1);
    lo = pack_bf2(s0 - h0, s1 - h1);
}
__device__ __forceinline__ void mma16816(float (&d)[4],
                                         unsigned a0, unsigned a1,
                                         unsigned a2, unsigned a3,
                                         unsigned b0, unsigned b1) {
    asm volatile(
        "mma.sync.aligned.m16n8k16.row.col.f32.bf16.bf16.f32 "
        "{%0,%1,%2,%3}, {%4,%5,%6,%7}, {%8,%9}, {%0,%1,%2,%3};"
        : "+f"(d[0]), "+f"(d[1]), "+f"(d[2]), "+f"(d[3])
        : "r"(a0), "r"(a1), "r"(a2), "r"(a3), "r"(b0), "r"(b1));
}

// ---------- prep 1: M = c2q(C) + Qn - I, zero-padded to NP x NP ----------
__global__ void prep_kernel(const float* __restrict__ C,
                            const float* __restrict__ Qn,
                            int n, int which)
{
    float* M = which ? g_M2 : g_M1;
    const int j = blockIdx.x;
    __shared__ float red[NTHREADS];
    float s = 0.f;
    if (j < n) {
        for (int i = threadIdx.x; i < n; i += NTHREADS)
            s += 0.5f * (C[i * n + j] + C[j * n + i]);
    }
    red[threadIdx.x] = s;
    __syncthreads();
    for (int off = NTHREADS / 2; off > 0; off >>= 1) {
        if (threadIdx.x < off) red[threadIdx.x] += red[threadIdx.x + off];
        __syncthreads();
    }
    const float colsum = red[0];
    for (int i = threadIdx.x; i < NP; i += NTHREADS) {
        float v = 0.f;
        if (j < n && i < n) {
            if (i == j) v = -colsum + Qn[j * n + j] - 1.0f;
            else        v = 0.5f * (C[i * n + j] + C[j * n + i]) + Qn[i * n + j];
        }
        M[i * NP + j] = v;
    }
}

// ---------- prep 2: pack M into mma b-fragment layout (hi/lo splits) ----------
// b0 of tile (kt,nt): B[k=16kt+2t+{0,1}][n=8nt+g]; b1: k offset +8. (g=lane>>2,t=lane&3)
__global__ void prep_frag(int which)
{
    const float* M = which ? g_M2 : g_M1;
    uint4* outB    = which ? g_B2 : g_B1;
    const int idx = blockIdx.x * blockDim.x + threadIdx.x;
    if (idx >= NKT * NNT * 32) return;
    const int lane = idx & 31;
    const int nt   = (idx >> 5) % NNT;
    const int kt   = (idx >> 5) / NNT;
    const int n  = nt * 8 + (lane >> 2);
    const int k0 = kt * 16 + (lane & 3) * 2;
    unsigned bh0, bl0, bh1, bl1;
    split2(M[k0 * NP + n],       M[(k0 + 1) * NP + n], bh0, bl0);
    split2(M[(k0 + 8) * NP + n], M[(k0 + 9) * NP + n], bh1, bl1);
    outB[(kt * NNT + nt) * 32 + lane] = make_uint4(bh0, bh1, bl0, bl1);
}

// ---------- main fused kernel ----------
__global__ void __launch_bounds__(NTHREADS, 1)
net_kernel(const float* __restrict__ x,
           const float* __restrict__ b1,
           const float* __restrict__ b2,
           const float* __restrict__ facp,
           float* __restrict__ out)
{
    extern __shared__ char smraw[];
    unsigned* Afrag = (unsigned*)smraw;                 // 4 rt * 13 kt * 8 slots * 32
    uint4*    Bs    = (uint4*)(Afrag + 4 * NKT * 8 * 32);
    float*    p_s   = (float*)(Bs + 2 * CHUNK_U4);      // 52 slots * 256 threads
    float*    es    = p_s + 52 * NTHREADS;              // NP bias

    const int tid  = threadIdx.x;
    const int lane = tid & 31, warp = tid >> 5;
    const int rt = warp & 3;        // row-tile (16 rows)
    const int h  = warp >> 2;       // col half (104 cols)
    const int g  = lane >> 2, t = lane & 3;
    const int rowg = blockIdx.x * TM;
    const int r0 = rt * 16 + g;     // owned local rows r0, r0+8

    float q[13][4];
    float acc[13][4];

    // init q = x (zero-padded); col pairs never straddle 196 (even boundary)
    #pragma unroll
    for (int nt = 0; nt < 13; nt++) {
        const int col = (h * 13 + nt) * 8 + 2 * t;
        if (col < D1) {
            const float2 v0 = *(const float2*)&x[(rowg + r0) * D1 + col];
            const float2 v1 = *(const float2*)&x[(rowg + r0 + 8) * D1 + col];
            q[nt][0] = v0.x; q[nt][1] = v0.y; q[nt][2] = v1.x; q[nt][3] = v1.y;
        } else {
            q[nt][0] = q[nt][1] = q[nt][2] = q[nt][3] = 0.f;
        }
    }
    for (int i = tid; i < NP; i += NTHREADS) es[i] = (i < D1) ? b1[i] : 0.f;
    __syncthreads();

    // sq = sin(1.1*q) -> bf16 hi/lo A-fragments in smem
    auto write_A = [&] {
        #pragma unroll
        for (int nt = 0; nt < 13; nt++) {
            const int NT = h * 13 + nt;
            const int kt = NT >> 1;
            const int rb = (NT & 1) ? 2 : 0;
            unsigned* base = &Afrag[((rt * 13 + kt) * 8) * 32 + lane];
            unsigned hi, lo;
            split2(__sinf(1.1f * q[nt][0]), __sinf(1.1f * q[nt][1]), hi, lo);
            base[rb * 32]       = hi;
            base[(rb + 4) * 32] = lo;
            split2(__sinf(1.1f * q[nt][2]), __sinf(1.1f * q[nt][3]), hi, lo);
            base[(rb + 1) * 32] = hi;
            base[(rb + 5) * 32] = lo;
        }
    };

    // acc = e + sq @ M  (bf16x3: ah*bh + ah*bl + al*bh), B streamed per k16 chunk
    auto gemm = [&](const uint4* __restrict__ Bg) {
        #pragma unroll
        for (int nt = 0; nt < 13; nt++) {
            const float2 e = *(const float2*)&es[(h * 13 + nt) * 8 + 2 * t];
            acc[nt][0] = e.x; acc[nt][1] = e.y; acc[nt][2] = e.x; acc[nt][3] = e.y;
        }
        for (int i = tid; i < CHUNK_U4; i += NTHREADS) Bs[i] = Bg[i];
        __syncthreads();                       // also orders write_A -> reads
        for (int kt = 0; kt < NKT; kt++) {
            if (kt + 1 < NKT) {
                const uint4* src = Bg + (kt + 1) * CHUNK_U4;
                uint4* dst = Bs + ((kt + 1) & 1) * CHUNK_U4;
                for (int i = tid; i < CHUNK_U4; i += NTHREADS) dst[i] = src[i];
            }
            const unsigned* Ab = &Afrag[((rt * 13 + kt) * 8) * 32 + lane];
            const unsigned ah0 = Ab[0],   ah1 = Ab[32],  ah2 = Ab[64],  ah3 = Ab[96];
            const unsigned al0 = Ab[128], al1 = Ab[160], al2 = Ab[192], al3 = Ab[224];
            const uint4* Bw = Bs + (kt & 1) * CHUNK_U4 + (h * 13) * 32 + lane;
            #pragma unroll
            for (int nt = 0; nt < 13; nt++) {
                const uint4 b = Bw[nt * 32];
                mma16816(acc[nt], ah0, ah1, ah2, ah3, b.x, b.y);  // ah*bh
                mma16816(acc[nt], ah0, ah1, ah2, ah3, b.z, b.w);  // ah*bl
                mma16816(acc[nt], al0, al1, al2, al3, b.x, b.y);  // al*bh
            }
            __syncthreads();
        }
    };

    #define PIDX(nt, j) ((nt) * 4 + (j)) * NTHREADS + tid

    // one PAT stage: evals at q0, q2, q3 (p0 = 0 algebra)
    auto stage = [&](const uint4* Bg) {
        // E0: q += dt^2*a ; p = 2dt*a
        write_A(); gemm(Bg);
        #pragma unroll
        for (int nt = 0; nt < 13; nt++)
            #pragma unroll
            for (int j = 0; j < 4; j++) {
                const float a = acc[nt][j];
                q[nt][j] += DT2 * a;
                p_s[PIDX(nt, j)] = 2.f * DT * a;
            }
        // E2: q += dt*p ; p += dt*a
        write_A(); gemm(Bg);
        #pragma unroll
        for (int nt = 0; nt < 13; nt++)
            #pragma unroll
            for (int j = 0; j < 4; j++) {
                const float po = p_s[PIDX(nt, j)];
                q[nt][j] += DT * po;
                p_s[PIDX(nt, j)] = po + DT * acc[nt][j];
            }
        // E3: q += 2dt*p + dt^2*a
        write_A(); gemm(Bg);
        #pragma unroll
        for (int nt = 0; nt < 13; nt++)
            #pragma unroll
            for (int j = 0; j < 4; j++)
                q[nt][j] += 2.f * DT * p_s[PIDX(nt, j)] + DT2 * acc[nt][j];
    };

    // ---- stage 1 ----
    stage(g_B1);

    // ---- stage 2: new bias; q pads (>=196) are still exactly 0; p overwritten at E0 ----
    __syncthreads();
    for (int i = tid; i < NP; i += NTHREADS) es[i] = (i < D2) ? b2[i] : 0.f;
    __syncthreads();
    stage(g_B2);

    // ---- output: cols 196..205 ----
    const float fac = *facp;
    if (h == 1) {
        #pragma unroll
        for (int nt = 11; nt < 13; nt++) {
            const int col0 = (13 + nt) * 8 + 2 * t;
            #pragma unroll
            for (int jj = 0; jj < 2; jj++) {
                const int col = col0 + jj;
                if (col >= 196 && col < D2) {
                    out[(rowg + r0) * 10 + (col - 196)]     = fac * q[nt][jj];
                    out[(rowg + r0 + 8) * 10 + (col - 196)] = fac * q[nt][2 + jj];
                }
            }
        }
    }
}

extern "C" void kernel_launch(void* const* d_in, const int* in_sizes, int n_in,
                              void* d_out, int out_size)
{
    const float* x    = (const float*)d_in[0];
    const float* fc1w = (const float*)d_in[1];
    const float* fc1b = (const float*)d_in[2];
    const float* fc2w = (const float*)d_in[3];
    const float* fc2b = (const float*)d_in[4];
    const float* fac  = (const float*)d_in[5];
    const float* qn1  = (const float*)d_in[6];
    const float* qn2  = (const float*)d_in[7];
    float* out = (float*)d_out;

    prep_kernel<<<NP, NTHREADS>>>(fc1w, qn1, D1, 0);
    prep_kernel<<<NP, NTHREADS>>>(fc2w, qn2, D2, 1);
    const int nfrag = NKT * NNT * 32;
    prep_frag<<<(nfrag + NTHREADS - 1) / NTHREADS, NTHREADS>>>(0);
    prep_frag<<<(nfrag + NTHREADS - 1) / NTHREADS, NTHREADS>>>(1);

    const int smem = (4 * NKT * 8 * 32) * 4      // A frags
                   + 2 * CHUNK_U4 * 16           // B double buffer
                   + 52 * NTHREADS * 4           // p
                   + NP * 4;                     // bias
    cudaFuncSetAttribute(net_kernel,
                         cudaFuncAttributeMaxDynamicSharedMemorySize, smem);
    net_kernel<<<BATCH / TM, NTHREADS, smem>>>(x, fc1b, fc2b, fac, out);
}

// round 7
// speedup vs baseline: 4.1281x; 3.1198x over previous
#include <cuda_runtime.h>
#include <cuda_bf16.h>

#define BATCH    65536
#define D1       196
#define D2       206
#define NP       208
#define TM       64          // batch rows per CTA
#define NTHREADS 256
#define DT2      0.01f
#define NKT      13          // k16 tiles
#define NNT      26          // n8 octets
#define CHUNK_U4 (NNT * 32)  // 832 uint4 per k16 chunk
#define B_U4     (NKT * CHUNK_U4)   // 10816 uint4 = 173056 B per stage
#define AFRAG_U32 (4 * NKT * 8 * 32) // 13312 u32 = 53248 B

__device__ float g_M1[NP * NP];
__device__ float g_M2[NP * NP];
__device__ uint4 g_B1[B_U4];   // pre-fragmented bf16 hi/lo B (stage 1)
__device__ uint4 g_B2[B_U4];   // stage 2

typedef unsigned u32;

// ---------- helpers ----------
__device__ __forceinline__ u32 pack_bf2(float lo, float hi) {
    __nv_bfloat162 v = __floats2bfloat162_rn(lo, hi);  // .x = lo (even k)
    return *reinterpret_cast<u32*>(&v);
}
__device__ __forceinline__ void split2(float s0, float s1, u32& hi, u32& lo) {
    float h0 = __bfloat162float(__float2bfloat16_rn(s0));
    float h1 = __bfloat162float(__float2bfloat16_rn(s1));
    hi = pack_bf2(h0, h1);
    lo = pack_bf2(s0 - h0, s1 - h1);
}
__device__ __forceinline__ void mma16816(float (&d)[4],
                                         u32 a0, u32 a1, u32 a2, u32 a3,
                                         u32 b0, u32 b1) {
    asm volatile(
        "mma.sync.aligned.m16n8k16.row.col.f32.bf16.bf16.f32 "
        "{%0,%1,%2,%3}, {%4,%5,%6,%7}, {%8,%9}, {%0,%1,%2,%3};"
        : "+f"(d[0]), "+f"(d[1]), "+f"(d[2]), "+f"(d[3])
        : "r"(a0), "r"(a1), "r"(a2), "r"(a3), "r"(b0), "r"(b1));
}
__device__ __forceinline__ u32 smem_u32(const void* p) {
    u32 a;
    asm("{ .reg .u64 t; cvta.to.shared.u64 t, %1; cvt.u32.u64 %0, t; }" : "=r"(a) : "l"(p));
    return a;
}
#define CP16(dst, src) asm volatile("cp.async.cg.shared.global [%0], [%1], 16;" :: "r"(dst), "l"(src) : "memory")
#define CP_WAIT() asm volatile("cp.async.commit_group;\ncp.async.wait_group 0;" ::: "memory")

// ---------- prep 1: M = c2q(C) + Qn - I, zero-padded to NP x NP ----------
__global__ void prep_kernel(const float* __restrict__ C,
                            const float* __restrict__ Qn, int n, int which)
{
    float* M = which ? g_M2 : g_M1;
    const int j = blockIdx.x;
    __shared__ float red[NTHREADS];
    float s = 0.f;
    if (j < n)
        for (int i = threadIdx.x; i < n; i += NTHREADS)
            s += 0.5f * (C[i * n + j] + C[j * n + i]);
    red[threadIdx.x] = s;
    __syncthreads();
    for (int off = NTHREADS / 2; off > 0; off >>= 1) {
        if ((int)threadIdx.x < off) red[threadIdx.x] += red[threadIdx.x + off];
        __syncthreads();
    }
    const float colsum = red[0];
    for (int i = threadIdx.x; i < NP; i += NTHREADS) {
        float v = 0.f;
        if (j < n && i < n) {
            if (i == j) v = -colsum + Qn[j * n + j] - 1.0f;
            else        v = 0.5f * (C[i * n + j] + C[j * n + i]) + Qn[i * n + j];
        }
        M[i * NP + j] = v;
    }
}

// ---------- prep 2: pack M into mma b-fragment layout (hi/lo splits) ----------
__global__ void prep_frag(int which)
{
    const float* M = which ? g_M2 : g_M1;
    uint4* outB    = which ? g_B2 : g_B1;
    const int idx = blockIdx.x * blockDim.x + threadIdx.x;
    if (idx >= NKT * NNT * 32) return;
    const int lane = idx & 31;
    const int nt   = (idx >> 5) % NNT;
    const int kt   = (idx >> 5) / NNT;
    const int n  = nt * 8 + (lane >> 2);
    const int k0 = kt * 16 + (lane & 3) * 2;
    u32 bh0, bl0, bh1, bl1;
    split2(M[k0 * NP + n],       M[(k0 + 1) * NP + n], bh0, bl0);
    split2(M[(k0 + 8) * NP + n], M[(k0 + 9) * NP + n], bh1, bl1);
    outB[(kt * NNT + nt) * 32 + lane] = make_uint4(bh0, bh1, bl0, bl1);
}

// ---------- main fused kernel ----------
__global__ void __launch_bounds__(NTHREADS, 1)
net_kernel(const float* __restrict__ x,
           const float* __restrict__ b1,
           const float* __restrict__ b2,
           const float* __restrict__ facp,
           float* __restrict__ out)
{
    extern __shared__ __align__(16) unsigned char smraw[];
    u32*   Afrag = (u32*)smraw;                                   // 53248 B
    uint4* Bs    = (uint4*)(smraw + AFRAG_U32 * 4);               // 173056 B
    float* es1   = (float*)(smraw + AFRAG_U32 * 4 + B_U4 * 16);   // 208 f
    float* es2   = es1 + NP;

    const int tid  = threadIdx.x;
    const int lane = tid & 31, warp = tid >> 5;
    const int rt = warp & 3;        // row-tile (16 rows)
    const int h  = warp >> 2;       // col half (104 cols)
    const int g  = lane >> 2, t = lane & 3;
    const int rowg = blockIdx.x * TM;
    const int r0 = rt * 16 + g;     // owned local rows r0, r0+8
    const u32 bsa = smem_u32(Bs);

    // start async copy of stage-1 B (never touched before first CP_WAIT)
    for (int i = tid; i < B_U4; i += NTHREADS)
        CP16(bsa + i * 16, (const uint4*)g_B1 + i);

    // biases for both stages
    for (int i = tid; i < NP; i += NTHREADS) {
        es1[i] = (i < D1) ? b1[i] : 0.f;
        es2[i] = (i < D2) ? b2[i] : 0.f;
    }

    float q[13][4];
    float acc[13][4];

    // q0 = x (zero-padded); col pairs never straddle 196 (even boundary)
    #pragma unroll
    for (int nt = 0; nt < 13; nt++) {
        const int col = (h * 13 + nt) * 8 + 2 * t;
        if (col < D1) {
            const float2 v0 = *(const float2*)&x[(size_t)(rowg + r0) * D1 + col];
            const float2 v1 = *(const float2*)&x[(size_t)(rowg + r0 + 8) * D1 + col];
            q[nt][0] = v0.x; q[nt][1] = v0.y; q[nt][2] = v1.x; q[nt][3] = v1.y;
        } else {
            q[nt][0] = q[nt][1] = q[nt][2] = q[nt][3] = 0.f;
        }
    }

    // write A = ws * sin(1.1 q) as bf16 hi/lo fragments (validated layout)
    auto write_A = [&](float ws) {
        #pragma unroll
        for (int nt = 0; nt < 13; nt++) {
            const int NT = h * 13 + nt;
            const int kt = NT >> 1;
            const int rb = (NT & 1) ? 2 : 0;
            u32* base = &Afrag[((rt * 13 + kt) * 8) * 32 + lane];
            u32 hi, lo;
            split2(ws * __sinf(1.1f * q[nt][0]), ws * __sinf(1.1f * q[nt][1]), hi, lo);
            base[rb * 32]       = hi;
            base[(rb + 4) * 32] = lo;
            split2(ws * __sinf(1.1f * q[nt][2]), ws * __sinf(1.1f * q[nt][3]), hi, lo);
            base[(rb + 1) * 32] = hi;
            base[(rb + 5) * 32] = lo;
        }
    };

    // acc += A @ M  (bf16x3: ah*bh + ah*bl + al*bh); B fully resident, no syncs
    auto gemm = [&] {
        #pragma unroll 1
        for (int kt = 0; kt < NKT; kt++) {
            const u32* Ab = &Afrag[((rt * 13 + kt) * 8) * 32 + lane];
            const u32 ah0 = Ab[0],   ah1 = Ab[32],  ah2 = Ab[64],  ah3 = Ab[96];
            const u32 al0 = Ab[128], al1 = Ab[160], al2 = Ab[192], al3 = Ab[224];
            const uint4* Bw = Bs + kt * CHUNK_U4 + (h * 13) * 32 + lane;
            #pragma unroll
            for (int nt = 0; nt < 13; nt++) {
                const uint4 b = Bw[nt * 32];
                mma16816(acc[nt], ah0, ah1, ah2, ah3, b.x, b.y);  // ah*bh
                mma16816(acc[nt], ah0, ah1, ah2, ah3, b.z, b.w);  // ah*bl
                mma16816(acc[nt], al0, al1, al2, al3, b.x, b.y);  // al*bh
            }
        }
    };

    const float fac = *facp;

    #pragma unroll 1
    for (int st = 0; st < 2; st++) {
        const float* es = st ? es2 : es1;
        #pragma unroll
        for (int nt = 0; nt < 13; nt++)
            #pragma unroll
            for (int j = 0; j < 4; j++) acc[nt][j] = 0.f;

        // ---- gemm 1: A = 4*s(q0) ----
        write_A(4.0f);
        if (st == 0) CP_WAIT();            // stage-1 B resident
        __syncthreads();                   // A + B visible
        gemm();
        __syncthreads();                   // all A reads done before overwrite

        // ---- readback (registers!): q2,q3; write A = u = 2*s(q2)+s(q3) ----
        #pragma unroll
        for (int nt = 0; nt < 13; nt++) {
            const int NT = h * 13 + nt;
            const int kt = NT >> 1;
            const int rb = (NT & 1) ? 2 : 0;
            u32* base = &Afrag[((rt * 13 + kt) * 8) * 32 + lane];
            float u[4];
            #pragma unroll
            for (int j = 0; j < 4; j++) {
                const int col = NT * 8 + 2 * t + (j & 1);
                const float a0v = es[col] + 0.25f * acc[nt][j];
                const float q2 = q[nt][j] + DT2 * a0v;
                q[nt][j] += 3.0f * DT2 * a0v;          // q := q3
                u[j] = 2.0f * __sinf(1.1f * q2) + __sinf(1.1f * q[nt][j]);
            }
            u32 hi, lo;
            split2(u[0], u[1], hi, lo);
            base[rb * 32]       = hi;
            base[(rb + 4) * 32] = lo;
            split2(u[2], u[3], hi, lo);
            base[(rb + 1) * 32] = hi;
            base[(rb + 5) * 32] = lo;
        }
        __syncthreads();

        // ---- gemm 2: acc += u @ M  (acc_final = (4 s0 + 2 s2 + s3) @ M) ----
        gemm();
        __syncthreads();                   // all B reads done before B swap

        if (st == 0) {
            // prefetch stage-2 B; overlapped with q5 + next write_A
            for (int i = tid; i < B_U4; i += NTHREADS)
                CP16(bsa + i * 16, (const uint4*)g_B2 + i);
        }

        // ---- q5 = q3 + dt^2*(7e + acc) ----
        #pragma unroll
        for (int nt = 0; nt < 13; nt++) {
            const int NT = h * 13 + nt;
            #pragma unroll
            for (int j = 0; j < 4; j++) {
                const int col = NT * 8 + 2 * t + (j & 1);
                const float q5 = q[nt][j] + DT2 * (7.0f * es[col] + acc[nt][j]);
                q[nt][j] = q5;
                if (st == 1 && col >= D1 && col < D2) {
                    const int row = rowg + r0 + ((j >> 1) << 3);
                    out[(size_t)row * 10 + (col - D1)] = fac * q5;
                }
            }
        }
        if (st == 0) CP_WAIT();            // stage-2 B resident (bar in next iter)
    }
}

extern "C" void kernel_launch(void* const* d_in, const int* in_sizes, int n_in,
                              void* d_out, int out_size)
{
    const float* x    = (const float*)d_in[0];
    const float* fc1w = (const float*)d_in[1];
    const float* fc1b = (const float*)d_in[2];
    const float* fc2w = (const float*)d_in[3];
    const float* fc2b = (const float*)d_in[4];
    const float* fac  = (const float*)d_in[5];
    const float* qn1  = (const float*)d_in[6];
    const float* qn2  = (const float*)d_in[7];
    float* out = (float*)d_out;

    prep_kernel<<<NP, NTHREADS>>>(fc1w, qn1, D1, 0);
    prep_kernel<<<NP, NTHREADS>>>(fc2w, qn2, D2, 1);
    const int nfrag = NKT * NNT * 32;
    prep_frag<<<(nfrag + NTHREADS - 1) / NTHREADS, NTHREADS>>>(0);
    prep_frag<<<(nfrag + NTHREADS - 1) / NTHREADS, NTHREADS>>>(1);

    const int smem = AFRAG_U32 * 4 + B_U4 * 16 + 2 * NP * 4;   // 227968 B
    cudaFuncSetAttribute(net_kernel,
                         cudaFuncAttributeMaxDynamicSharedMemorySize, smem);
    net_kernel<<<BATCH / TM, NTHREADS, smem>>>(x, fc1b, fc2b, fac, out);
}

// round 8
// speedup vs baseline: 6.1001x; 1.4777x over previous
#include <cuda_runtime.h>
#include <cuda_fp16.h>

#define BATCH    65536
#define D1       196
#define D2       206
#define NP       208
#define TM       64          // batch rows per CTA
#define NTHREADS 256
#define DT2      0.01f
#define NKT      13          // k16 tiles
#define NNT      26          // n8 octets
#define CHUNK_U4 (NNT * 32)  // 832 uint4 per k16 chunk
#define B_U4     (NKT * CHUNK_U4)    // 10816 uint4 = 173056 B per stage
#define AFRAG_U32 (4 * NKT * 4 * 32) // 6656 u32 = 26624 B

__device__ float g_M1[NP * NP];
__device__ float g_M2[NP * NP];
__device__ uint4 g_B1[B_U4];   // pre-fragmented fp16 hi/lo B (stage 1)
__device__ uint4 g_B2[B_U4];   // stage 2

typedef unsigned u32;

// ---------- helpers ----------
__device__ __forceinline__ u32 pack_h2(float lo, float hi) {
    __half2 v = __floats2half2_rn(lo, hi);   // .x = lo (even k)
    return *reinterpret_cast<u32*>(&v);
}
__device__ __forceinline__ void split2h(float v0, float v1, u32& hi, u32& lo) {
    __half h0 = __float2half_rn(v0);
    __half h1 = __float2half_rn(v1);
    __half2 hh = __halves2half2(h0, h1);
    hi = *reinterpret_cast<u32*>(&hh);
    __half2 ll = __floats2half2_rn(v0 - __half2float(h0), v1 - __half2float(h1));
    lo = *reinterpret_cast<u32*>(&ll);
}
__device__ __forceinline__ void mma16816h(float (&d)[4],
                                          u32 a0, u32 a1, u32 a2, u32 a3,
                                          u32 b0, u32 b1) {
    asm volatile(
        "mma.sync.aligned.m16n8k16.row.col.f32.f16.f16.f32 "
        "{%0,%1,%2,%3}, {%4,%5,%6,%7}, {%8,%9}, {%0,%1,%2,%3};"
        : "+f"(d[0]), "+f"(d[1]), "+f"(d[2]), "+f"(d[3])
        : "r"(a0), "r"(a1), "r"(a2), "r"(a3), "r"(b0), "r"(b1));
}
__device__ __forceinline__ u32 smem_u32(const void* p) {
    u32 a;
    asm("{ .reg .u64 t; cvta.to.shared.u64 t, %1; cvt.u32.u64 %0, t; }" : "=r"(a) : "l"(p));
    return a;
}
#define CP16(dst, src) asm volatile("cp.async.cg.shared.global [%0], [%1], 16;" :: "r"(dst), "l"(src) : "memory")
#define CP_WAIT() asm volatile("cp.async.commit_group;\ncp.async.wait_group 0;" ::: "memory")

// ---------- prep 1: M = c2q(C) + Qn - I, zero-padded to NP x NP ----------
__global__ void prep_kernel(const float* __restrict__ C,
                            const float* __restrict__ Qn, int n, int which)
{
    float* M = which ? g_M2 : g_M1;
    const int j = blockIdx.x;
    __shared__ float red[NTHREADS];
    float s = 0.f;
    if (j < n)
        for (int i = threadIdx.x; i < n; i += NTHREADS)
            s += 0.5f * (C[i * n + j] + C[j * n + i]);
    red[threadIdx.x] = s;
    __syncthreads();
    for (int off = NTHREADS / 2; off > 0; off >>= 1) {
        if ((int)threadIdx.x < off) red[threadIdx.x] += red[threadIdx.x + off];
        __syncthreads();
    }
    const float colsum = red[0];
    for (int i = threadIdx.x; i < NP; i += NTHREADS) {
        float v = 0.f;
        if (j < n && i < n) {
            if (i == j) v = -colsum + Qn[j * n + j] - 1.0f;
            else        v = 0.5f * (C[i * n + j] + C[j * n + i]) + Qn[i * n + j];
        }
        M[i * NP + j] = v;
    }
}

// ---------- prep 2: pack M into mma b-fragment layout (fp16 hi/lo splits) ----------
__global__ void prep_frag(int which)
{
    const float* M = which ? g_M2 : g_M1;
    uint4* outB    = which ? g_B2 : g_B1;
    const int idx = blockIdx.x * blockDim.x + threadIdx.x;
    if (idx >= NKT * NNT * 32) return;
    const int lane = idx & 31;
    const int nt   = (idx >> 5) % NNT;
    const int kt   = (idx >> 5) / NNT;
    const int n  = nt * 8 + (lane >> 2);
    const int k0 = kt * 16 + (lane & 3) * 2;
    u32 bh0, bl0, bh1, bl1;
    split2h(M[k0 * NP + n],       M[(k0 + 1) * NP + n], bh0, bl0);
    split2h(M[(k0 + 8) * NP + n], M[(k0 + 9) * NP + n], bh1, bl1);
    outB[(kt * NNT + nt) * 32 + lane] = make_uint4(bh0, bh1, bl0, bl1);
}

// ---------- main fused kernel ----------
__global__ void __launch_bounds__(NTHREADS, 1)
net_kernel(const float* __restrict__ x,
           const float* __restrict__ b1,
           const float* __restrict__ b2,
           const float* __restrict__ facp,
           float* __restrict__ out)
{
    extern __shared__ __align__(16) unsigned char smraw[];
    u32*   Afrag = (u32*)smraw;                                   // 26624 B
    uint4* Bs    = (uint4*)(smraw + AFRAG_U32 * 4);               // 173056 B
    float* es1   = (float*)(smraw + AFRAG_U32 * 4 + B_U4 * 16);   // 208 f
    float* es2   = es1 + NP;

    const int tid  = threadIdx.x;
    const int lane = tid & 31, warp = tid >> 5;
    const int rt = warp & 3;        // row-tile (16 rows)
    const int h  = warp >> 2;       // col half (104 cols)
    const int g  = lane >> 2, t = lane & 3;
    const int rowg = blockIdx.x * TM;
    const int r0 = rt * 16 + g;     // owned local rows r0, r0+8
    const u32 bsa = smem_u32(Bs);

    // start async copy of stage-1 B (never touched before first CP_WAIT)
    for (int i = tid; i < B_U4; i += NTHREADS)
        CP16(bsa + i * 16, (const uint4*)g_B1 + i);

    // biases for both stages
    for (int i = tid; i < NP; i += NTHREADS) {
        es1[i] = (i < D1) ? b1[i] : 0.f;
        es2[i] = (i < D2) ? b2[i] : 0.f;
    }

    float q[13][4];
    float acc[13][4];

    // q0 = x (zero-padded); col pairs never straddle 196 (even boundary)
    #pragma unroll
    for (int nt = 0; nt < 13; nt++) {
        const int col = (h * 13 + nt) * 8 + 2 * t;
        if (col < D1) {
            const float2 v0 = *(const float2*)&x[(size_t)(rowg + r0) * D1 + col];
            const float2 v1 = *(const float2*)&x[(size_t)(rowg + r0 + 8) * D1 + col];
            q[nt][0] = v0.x; q[nt][1] = v0.y; q[nt][2] = v1.x; q[nt][3] = v1.y;
        } else {
            q[nt][0] = q[nt][1] = q[nt][2] = q[nt][3] = 0.f;
        }
    }

    // write A = ws * sin(1.1 q) as single-fp16 fragments
    auto write_A = [&](float ws) {
        #pragma unroll
        for (int nt = 0; nt < 13; nt++) {
            const int NT = h * 13 + nt;
            const int kt = NT >> 1;
            const int rb = (NT & 1) ? 2 : 0;
            u32* base = &Afrag[((rt * 13 + kt) * 4) * 32 + lane];
            base[rb * 32] =
                pack_h2(ws * __sinf(1.1f * q[nt][0]), ws * __sinf(1.1f * q[nt][1]));
            base[(rb + 1) * 32] =
                pack_h2(ws * __sinf(1.1f * q[nt][2]), ws * __sinf(1.1f * q[nt][3]));
        }
    };

    // acc += A @ M  (fp16 2-term: a*bh + a*bl); B fully resident, no syncs
    auto gemm_full = [&] {
        #pragma unroll 1
        for (int kt = 0; kt < NKT; kt++) {
            const u32* Ab = &Afrag[((rt * 13 + kt) * 4) * 32 + lane];
            const u32 a0 = Ab[0], a1 = Ab[32], a2 = Ab[64], a3 = Ab[96];
            const uint4* Bw = Bs + kt * CHUNK_U4 + (h * 13) * 32 + lane;
            #pragma unroll
            for (int nt = 0; nt < 13; nt++) {
                const uint4 b = Bw[nt * 32];
                mma16816h(acc[nt], a0, a1, a2, a3, b.x, b.y);  // a*bh
                mma16816h(acc[nt], a0, a1, a2, a3, b.z, b.w);  // a*bl
            }
        }
    };
    // skinny: only n-tiles 24,25 (cols 192..207) -> h==1 warps, nt 11..12
    auto gemm_skinny = [&] {
        if (h == 1) {
            #pragma unroll 1
            for (int kt = 0; kt < NKT; kt++) {
                const u32* Ab = &Afrag[((rt * 13 + kt) * 4) * 32 + lane];
                const u32 a0 = Ab[0], a1 = Ab[32], a2 = Ab[64], a3 = Ab[96];
                const uint4* Bw = Bs + kt * CHUNK_U4 + 13 * 32 + lane;
                #pragma unroll
                for (int nt = 11; nt < 13; nt++) {
                    const uint4 b = Bw[nt * 32];
                    mma16816h(acc[nt], a0, a1, a2, a3, b.x, b.y);
                    mma16816h(acc[nt], a0, a1, a2, a3, b.z, b.w);
                }
            }
        }
    };

    const float fac = *facp;

    #pragma unroll 1
    for (int st = 0; st < 2; st++) {
        const float* es = st ? es2 : es1;
        #pragma unroll
        for (int nt = 0; nt < 13; nt++)
            #pragma unroll
            for (int j = 0; j < 4; j++) acc[nt][j] = 0.f;

        // ---- gemm 1: A = 4*s(q0) ----
        write_A(4.0f);
        if (st == 0) CP_WAIT();            // stage-1 B resident
        __syncthreads();                   // A + B visible
        gemm_full();
        __syncthreads();                   // all A reads done before overwrite

        // ---- readback (registers): q2,q3; write A = u = 2*s(q2)+s(q3) ----
        #pragma unroll
        for (int nt = 0; nt < 13; nt++) {
            const int NT = h * 13 + nt;
            const int kt = NT >> 1;
            const int rb = (NT & 1) ? 2 : 0;
            u32* base = &Afrag[((rt * 13 + kt) * 4) * 32 + lane];
            float u[4];
            #pragma unroll
            for (int j = 0; j < 4; j++) {
                const int col = NT * 8 + 2 * t + (j & 1);
                const float a0v = es[col] + 0.25f * acc[nt][j];
                const float q2 = q[nt][j] + DT2 * a0v;
                q[nt][j] += 3.0f * DT2 * a0v;          // q := q3
                u[j] = 2.0f * __sinf(1.1f * q2) + __sinf(1.1f * q[nt][j]);
            }
            base[rb * 32]       = pack_h2(u[0], u[1]);
            base[(rb + 1) * 32] = pack_h2(u[2], u[3]);
        }
        __syncthreads();

        // ---- gemm 2: acc += u @ M  (acc_final = (4 s0 + 2 s2 + s3) @ M) ----
        if (st == 0) gemm_full();
        else         gemm_skinny();
        __syncthreads();                   // all B reads done before B swap

        if (st == 0) {
            // prefetch stage-2 B; overlapped with q5 + next write_A
            for (int i = tid; i < B_U4; i += NTHREADS)
                CP16(bsa + i * 16, (const uint4*)g_B2 + i);
            // q5 = q3 + dt^2*(7e + acc) for all columns (feeds stage 2)
            #pragma unroll
            for (int nt = 0; nt < 13; nt++) {
                const int NT = h * 13 + nt;
                #pragma unroll
                for (int j = 0; j < 4; j++) {
                    const int col = NT * 8 + 2 * t + (j & 1);
                    q[nt][j] += DT2 * (7.0f * es[col] + acc[nt][j]);
                }
            }
            CP_WAIT();                     // stage-2 B resident (bar in next iter)
        } else {
            // output: q5 only for cols 196..205 (h==1, nt 11,12)
            if (h == 1) {
                #pragma unroll
                for (int nt = 11; nt < 13; nt++) {
                    const int NT = 13 + nt;
                    #pragma unroll
                    for (int j = 0; j < 4; j++) {
                        const int col = NT * 8 + 2 * t + (j & 1);
                        if (col >= D1 && col < D2) {
                            const float q5 = q[nt][j]
                                + DT2 * (7.0f * es[col] + acc[nt][j]);
                            const int row = rowg + r0 + ((j >> 1) << 3);
                            out[(size_t)row * 10 + (col - D1)] = fac * q5;
                        }
                    }
                }
            }
        }
    }
}

extern "C" void kernel_launch(void* const* d_in, const int* in_sizes, int n_in,
                              void* d_out, int out_size)
{
    const float* x    = (const float*)d_in[0];
    const float* fc1w = (const float*)d_in[1];
    const float* fc1b = (const float*)d_in[2];
    const float* fc2w = (const float*)d_in[3];
    const float* fc2b = (const float*)d_in[4];
    const float* fac  = (const float*)d_in[5];
    const float* qn1  = (const float*)d_in[6];
    const float* qn2  = (const float*)d_in[7];
    float* out = (float*)d_out;

    prep_kernel<<<NP, NTHREADS>>>(fc1w, qn1, D1, 0);
    prep_kernel<<<NP, NTHREADS>>>(fc2w, qn2, D2, 1);
    const int nfrag = NKT * NNT * 32;
    prep_frag<<<(nfrag + NTHREADS - 1) / NTHREADS, NTHREADS>>>(0);
    prep_frag<<<(nfrag + NTHREADS - 1) / NTHREADS, NTHREADS>>>(1);

    const int smem = AFRAG_U32 * 4 + B_U4 * 16 + 2 * NP * 4;
    cudaFuncSetAttribute(net_kernel,
                         cudaFuncAttributeMaxDynamicSharedMemorySize, smem);
    net_kernel<<<BATCH / TM, NTHREADS, smem>>>(x, fc1b, fc2b, fac, out);
}